// round 11
// baseline (speedup 1.0000x reference)
#include <cuda_runtime.h>
#include <math.h>

#define NB      16
#define NPTS    4096
#define G       32
#define NCELL   (G * G * G)          // 32768 cells per batch per set
#define H       0.25f
#define ORIG    (-4.0f)
#define EPS     1e-6f
#define TOTAL_Q (NB * NPTS)          // 65536 per direction

// Scratch (no cudaMalloc allowed). set 0 = x, set 1 = y.
__device__ float4   g_sorted[2][NB * NPTS];        // counting-sorted points
__device__ unsigned g_cnt   [2][NB][NCELL];
__device__ unsigned g_start [2][NB][NCELL + 1];    // batch-local exclusive prefix
__device__ unsigned g_cursor[2][NB][NCELL];

__device__ __forceinline__ int clampi(int v, int lo, int hi) {
    return v < lo ? lo : (v > hi ? hi : v);
}
__device__ __forceinline__ int bin1(float v) {
    return clampi((int)floorf((v - ORIG) * (1.0f / H)), 0, G - 1);
}
__device__ __forceinline__ int cell_of(float x, float y, float z) {
    return (bin1(z) * G + bin1(y)) * G + bin1(x);
}
// Axis distance from query coord to cell c's slab; boundary cells are
// unbounded OUTWARD (clamped outliers live there) so the bound stays valid.
__device__ __forceinline__ float axdist(float v, int c) {
    float lo = ORIG + c * H;
    float hi = lo + H;
    float d = 0.0f;
    if (v < lo) { if (c > 0)     d = lo - v; }
    else if (v > hi) { if (c < G - 1) d = v - hi; }
    return d;
}

// ---------------------------------------------------------------------------
__global__ void init_kernel(float* __restrict__ out) {
    int tid = blockIdx.x * blockDim.x + threadIdx.x;
    if (tid == 0) out[0] = 0.0f;
    unsigned* base = &g_cnt[0][0][0];
    const int total = 2 * NB * NCELL;
    for (int i = tid; i < total; i += gridDim.x * blockDim.x) base[i] = 0u;
}

// ---------------------------------------------------------------------------
__global__ void count_kernel(const float* __restrict__ x,
                             const float* __restrict__ y) {
    int idx = blockIdx.x * blockDim.x + threadIdx.x;
    if (idx >= NB * NPTS) return;
    int b = idx >> 12;
    const float* px = x + (size_t)idx * 3;
    atomicAdd(&g_cnt[0][b][cell_of(px[0], px[1], px[2])], 1u);
    const float* py = y + (size_t)idx * 3;
    atomicAdd(&g_cnt[1][b][cell_of(py[0], py[1], py[2])], 1u);
}

// ---------------------------------------------------------------------------
// One block per (set, batch): 1024 threads x 32 cells each, Hillis-Steele
// block scan -> batch-local exclusive prefix.
// ---------------------------------------------------------------------------
__global__ void scan_kernel() {
    int sb  = blockIdx.x;
    int set = sb >> 4, b = sb & 15;
    const unsigned* cnt = g_cnt[set][b];
    unsigned* start = g_start[set][b];
    unsigned* cur   = g_cursor[set][b];
    int t = threadIdx.x;

    unsigned local[32], s = 0;
#pragma unroll
    for (int k = 0; k < 32; k++) { local[k] = cnt[t * 32 + k]; s += local[k]; }

    __shared__ unsigned sh[1024];
    sh[t] = s; __syncthreads();
    for (int off = 1; off < 1024; off <<= 1) {
        unsigned v = (t >= off) ? sh[t - off] : 0u;
        __syncthreads();
        sh[t] += v;
        __syncthreads();
    }
    unsigned run = sh[t] - s;   // exclusive prefix
#pragma unroll
    for (int k = 0; k < 32; k++) {
        start[t * 32 + k] = run;
        cur[t * 32 + k]   = run;
        run += local[k];
    }
    if (t == 1023) start[NCELL] = run;   // == NPTS
}

// ---------------------------------------------------------------------------
__global__ void scatter_kernel(const float* __restrict__ x,
                               const float* __restrict__ y) {
    int idx = blockIdx.x * blockDim.x + threadIdx.x;
    if (idx >= NB * NPTS) return;
    int b = idx >> 12;
    {
        const float* p = x + (size_t)idx * 3;
        float a = p[0], c = p[1], d = p[2];
        unsigned pos = atomicAdd(&g_cursor[0][b][cell_of(a, c, d)], 1u);
        g_sorted[0][(b << 12) + pos] = make_float4(a, c, d, 0.0f);
    }
    {
        const float* p = y + (size_t)idx * 3;
        float a = p[0], c = p[1], d = p[2];
        unsigned pos = atomicAdd(&g_cursor[1][b][cell_of(a, c, d)], 1u);
        g_sorted[1][(b << 12) + pos] = make_float4(a, c, d, 0.0f);
    }
}

// ---------------------------------------------------------------------------
// Query: thread = one sorted point (warp-coherent cells). dir 0: query x vs
// y-grid (min1); dir 1: query y vs x-grid (min2). Exact NN via expanding
// shells with box-distance pruning.
// ---------------------------------------------------------------------------
__global__ __launch_bounds__(256)
void query_kernel(float* __restrict__ out) {
    int tid = blockIdx.x * blockDim.x + threadIdx.x;   // 0 .. 2*65536-1
    int dir = tid >> 16;
    int rem = tid & 65535;         // = b*4096 + i (sorted order within batch)
    int b   = rem >> 12;

    float4 q = g_sorted[dir][rem];

    const float4*   cand = g_sorted[1 - dir] + (b << 12);
    const unsigned* cs   = g_start[1 - dir][b];

    const int qcx = bin1(q.x), qcy = bin1(q.y), qcz = bin1(q.z);
    float best2 = 3.4e38f;

    // r = 0..1 cube (27 cells, no pruning — best2 still huge)
    for (int dz = -1; dz <= 1; dz++) {
        int cz = qcz + dz; if (cz < 0 || cz >= G) continue;
        for (int dy = -1; dy <= 1; dy++) {
            int cy = qcy + dy; if (cy < 0 || cy >= G) continue;
            for (int dx = -1; dx <= 1; dx++) {
                int cx = qcx + dx; if (cx < 0 || cx >= G) continue;
                int c = (cz * G + cy) * G + cx;
                unsigned s = cs[c], e = cs[c + 1];
                for (unsigned j = s; j < e; j++) {
                    float4 p = cand[j];
                    float ddx = q.x - p.x, ddy = q.y - p.y, ddz = q.z - p.z;
                    float d2 = fmaf(ddx, ddx, fmaf(ddy, ddy, ddz * ddz));
                    best2 = fminf(best2, d2);
                }
            }
        }
    }

    // Expanding shells r >= 2 with box-distance pruning
    for (int r = 2; r <= G; r++) {
        float bnd = (float)(r - 1) * H;
        if (bnd * bnd >= best2) break;
        for (int dz = -r; dz <= r; dz++) {
            int cz = qcz + dz; if (cz < 0 || cz >= G) continue;
            int adz = dz < 0 ? -dz : dz;
            float bz = axdist(q.z, cz);
            float bz2 = bz * bz;
            if (bz2 >= best2) continue;
            for (int dy = -r; dy <= r; dy++) {
                int cy = qcy + dy; if (cy < 0 || cy >= G) continue;
                int ady = dy < 0 ? -dy : dy;
                float by = axdist(q.y, cy);
                float byz2 = fmaf(by, by, bz2);
                if (byz2 >= best2) continue;
                // Interior of the cube was covered at smaller r: only x-extremes
                // unless this (dy,dz) line is on the shell surface.
                int dxstep = (adz == r || ady == r) ? 1 : 2 * r;
                for (int dx = -r; dx <= r; dx += dxstep) {
                    int cx = qcx + dx; if (cx < 0 || cx >= G) continue;
                    float bx = axdist(q.x, cx);
                    float bd2 = fmaf(bx, bx, byz2);
                    if (bd2 >= best2) continue;
                    int c = (cz * G + cy) * G + cx;
                    unsigned s = cs[c], e = cs[c + 1];
                    for (unsigned j = s; j < e; j++) {
                        float4 p = cand[j];
                        float ddx = q.x - p.x, ddy = q.y - p.y, ddz = q.z - p.z;
                        float d2 = fmaf(ddx, ddx, fmaf(ddy, ddy, ddz * ddz));
                        best2 = fminf(best2, d2);
                    }
                }
            }
        }
    }

    float local = sqrtf(EPS + best2);   // best2 >= 0 by construction

    // Block reduction (256 threads = 8 warps) + scaled atomic
#pragma unroll
    for (int o = 16; o > 0; o >>= 1)
        local += __shfl_down_sync(0xFFFFFFFFu, local, o);

    __shared__ float warp_sums[8];
    int lane = threadIdx.x & 31;
    int wid  = threadIdx.x >> 5;
    if (lane == 0) warp_sums[wid] = local;
    __syncthreads();
    if (wid == 0) {
        float sv = (lane < 8) ? warp_sums[lane] : 0.0f;
#pragma unroll
        for (int o = 4; o > 0; o >>= 1)
            sv += __shfl_down_sync(0xFFFFFFFFu, sv, o);
        if (lane == 0) atomicAdd(out, sv * (1.0f / (float)TOTAL_Q));
    }
}

extern "C" void kernel_launch(void* const* d_in, const int* in_sizes, int n_in,
                              void* d_out, int out_size) {
    const float* x = (const float*)d_in[0];
    const float* y = (const float*)d_in[1];
    float* out = (float*)d_out;

    init_kernel<<<1024, 256>>>(out);
    count_kernel<<<(NB * NPTS + 255) / 256, 256>>>(x, y);
    scan_kernel<<<32, 1024>>>();
    scatter_kernel<<<(NB * NPTS + 255) / 256, 256>>>(x, y);
    query_kernel<<<(2 * NB * NPTS) / 256, 256>>>(out);
}

// round 12
// speedup vs baseline: 5.4638x; 5.4638x over previous
#include <cuda_runtime.h>
#include <math.h>

#define NB       16
#define NPTS     4096
#define C        8                        // candidates per thread (register-resident)
#define THREADS  128
#define WARPS    (THREADS / 32)
#define CANDS_PER_BLOCK (THREADS * C)     // 1024
#define CCHUNKS  (NPTS / CANDS_PER_BLOCK) // 4
#define ROWSPLIT 64
#define ROWS_PER_BLOCK (NPTS / ROWSPLIT)  // 64
#define RPAIRS   (ROWS_PER_BLOCK / 2)     // 32
#define GROUPS   4                        // 4 groups of 16 rows per tile
#define TPG      (RPAIRS / GROUPS)        // 8 row-pair iters per group
#define NTILES   (CCHUNKS * ROWSPLIT * NB)  // 4096
#define NBLOCKS  592                      // 148 SMs x occ 4 -> single wave
#define EPS      1e-6f
#define TOTAL_Q  (NB * NPTS)

// Scratch (no cudaMalloc allowed)
__device__ float4   g_rowpair[NB * NPTS];      // pair 2k:(x0,x1,y0,y1) 2k+1:(z0,z1,w0,w1)
__device__ float4   g_col[NB * NPTS];          // (-2x, -2y, -2z, ||x||^2)
__device__ unsigned g_rowmin[NB * NPTS];
__device__ unsigned g_colmin[NB * NPTS];

__device__ __forceinline__ unsigned flipf(float f) {
    unsigned b = __float_as_uint(f);
    return b ^ (0x80000000u | (unsigned)((int)b >> 31));
}
__device__ __forceinline__ float unflipf(unsigned u) {
    unsigned b = (u & 0x80000000u) ? (u ^ 0x80000000u) : ~u;
    return __uint_as_float(b);
}
__device__ __forceinline__ unsigned long long pack2(float a, float b) {
    unsigned long long r;
    asm("mov.b64 %0, {%1, %2};" : "=l"(r) : "f"(a), "f"(b));
    return r;
}
__device__ __forceinline__ float fmin3(float a, float b, float c) {
    float r;
    asm("min.f32 %0, %1, %2, %3;" : "=f"(r) : "f"(a), "f"(b), "f"(c));
    return r;
}

// ---------------------------------------------------------------------------
// Pack kernel: thread k handles 4 consecutive points (= 2 row pairs) of each
// tensor via 3 coalesced float4 loads per tensor.
// ---------------------------------------------------------------------------
__global__ void pack_kernel(const float* __restrict__ x,
                            const float* __restrict__ y,
                            float* __restrict__ out) {
    int k = blockIdx.x * blockDim.x + threadIdx.x;   // quad index
    if (k == 0) out[0] = 0.0f;
    if (k >= NB * NPTS / 4) return;

    // ---- rows (y points) ----
    {
        const float4* p = (const float4*)(y) + 3 * k;   // 12 floats = 4 points
        float4 a = p[0], b = p[1], c = p[2];
        // points: (a.x,a.y,a.z) (a.w,b.x,b.y) (b.z,b.w,c.x) (c.y,c.z,c.w)
        float w0 = a.x * a.x + a.y * a.y + a.z * a.z;
        float w1 = a.w * a.w + b.x * b.x + b.y * b.y;
        float w2 = b.z * b.z + b.w * b.w + c.x * c.x;
        float w3 = c.y * c.y + c.z * c.z + c.w * c.w;
        float4* dst = g_rowpair + 4 * k;
        dst[0] = make_float4(a.x, a.w, a.y, b.x);   // pair0: x0,x1,y0,y1
        dst[1] = make_float4(a.z, b.y, w0, w1);     // pair0: z0,z1,w0,w1
        dst[2] = make_float4(b.z, c.y, b.w, c.z);   // pair1: x0,x1,y0,y1
        dst[3] = make_float4(c.x, c.w, w2, w3);     // pair1: z0,z1,w0,w1
    }
    // ---- cols (x points) ----
    {
        const float4* p = (const float4*)(x) + 3 * k;
        float4 a = p[0], b = p[1], c = p[2];
        float4* dst = g_col + 4 * k;
        dst[0] = make_float4(-2.f * a.x, -2.f * a.y, -2.f * a.z,
                             a.x * a.x + a.y * a.y + a.z * a.z);
        dst[1] = make_float4(-2.f * a.w, -2.f * b.x, -2.f * b.y,
                             a.w * a.w + b.x * b.x + b.y * b.y);
        dst[2] = make_float4(-2.f * b.z, -2.f * b.w, -2.f * c.x,
                             b.z * b.z + b.w * b.w + c.x * c.x);
        dst[3] = make_float4(-2.f * c.y, -2.f * c.z, -2.f * c.w,
                             c.y * c.y + c.z * c.z + c.w * c.w);
    }
    // ---- init min buffers (4 each) ----
    uint4* rm = (uint4*)(g_rowmin + 4 * k);
    uint4* cm = (uint4*)(g_colmin + 4 * k);
    rm[0] = make_uint4(~0u, ~0u, ~0u, ~0u);
    cm[0] = make_uint4(~0u, ~0u, ~0u, ~0u);
}

// ---------------------------------------------------------------------------
// Fused pass: persistent grid of NBLOCKS blocks, each loops over tiles.
// Tile = (b, cc, rs): candidates (cc,b) in registers, 64-row slice (rs,b)
// streamed from smem. Inner loop identical to R8 (proven):
// per 2 rows x 512 pairs: 32 FFMA2/FADD2 + 8 mov + 16 min3/min.
// ---------------------------------------------------------------------------
__global__ __launch_bounds__(THREADS, 4)
void chamfer_fused_kernel() {
    __shared__ float4 rowtile[RPAIRS * 2];             // 1 KB
    __shared__ float  tbuf[WARPS][16 * 33];            // padded stride 33

    const int lane = threadIdx.x & 31;
    const int wid  = threadIdx.x >> 5;
    float* tb = tbuf[wid];
    const ulonglong2* tp = (const ulonglong2*)rowtile;

    for (int tile = blockIdx.x; tile < NTILES; tile += NBLOCKS) {
        const int rs = tile & (ROWSPLIT - 1);
        const int t2 = tile >> 6;              // / ROWSPLIT
        const int cc = t2 & (CCHUNKS - 1);
        const int b  = t2 >> 2;                // / CCHUNKS

        const int row0 = rs * ROWS_PER_BLOCK;
        const int j0   = cc * CANDS_PER_BLOCK + threadIdx.x * C;

        const float4* __restrict__ RPbase = g_rowpair + (size_t)b * NPTS + row0;
        const float4* __restrict__ Cd     = g_col     + (size_t)b * NPTS + j0;

        // Load candidates, duplicate into packed 64-bit registers
        unsigned long long cxd[C], cyd[C], czd[C], cwd[C];
        float cm[C];
#pragma unroll
        for (int c = 0; c < C; c++) {
            float4 f = Cd[c];
            cxd[c] = pack2(f.x, f.x);
            cyd[c] = pack2(f.y, f.y);
            czd[c] = pack2(f.z, f.z);
            cwd[c] = pack2(f.w, f.w);
            cm[c]  = 3.4e38f;
        }

        // Stage row slice (sync first: rowtile may still be read by prev tile)
        __syncthreads();
        for (int i = threadIdx.x; i < RPAIRS * 2; i += THREADS)
            rowtile[i] = RPbase[i];
        __syncthreads();

        for (int g = 0; g < GROUPS; g++) {
            float r0s[TPG], r1s[TPG];

#pragma unroll
            for (int t = 0; t < TPG; t++) {
                const int rp = g * TPG + t;
                ulonglong2 e0 = tp[2 * rp + 0];   // .x = xpair, .y = ypair
                ulonglong2 e1 = tp[2 * rp + 1];   // .x = zpair, .y = wpair (y2)

                float v0s[C], v1s[C];
#pragma unroll
                for (int c = 0; c < C; c++) {
                    unsigned long long t64;
                    asm("fma.rn.f32x2 %0, %1, %2, %3;" : "=l"(t64) : "l"(e1.x), "l"(czd[c]), "l"(cwd[c]));
                    asm("fma.rn.f32x2 %0, %1, %2, %0;" : "+l"(t64) : "l"(e0.y), "l"(cyd[c]));
                    asm("fma.rn.f32x2 %0, %1, %2, %0;" : "+l"(t64) : "l"(e0.x), "l"(cxd[c]));
                    asm("add.rn.f32x2 %0, %0, %1;"     : "+l"(t64) : "l"(e1.y));
                    float v0, v1;
                    asm("mov.b64 {%0, %1}, %2;" : "=f"(v0), "=f"(v1) : "l"(t64));
                    v0s[c] = v0; v1s[c] = v1;
                    cm[c] = fmin3(cm[c], v0, v1);
                }
                r0s[t] = fmin3(fmin3(v0s[0], v0s[1], v0s[2]),
                               fmin3(v0s[3], v0s[4], v0s[5]),
                               fminf(v0s[6], v0s[7]));
                r1s[t] = fmin3(fmin3(v1s[0], v1s[1], v1s[2]),
                               fmin3(v1s[3], v1s[4], v1s[5]),
                               fminf(v1s[6], v1s[7]));
            }

            // ---- Transpose-reduce 16 rows x 32 lanes (per warp) ----
#pragma unroll
            for (int t = 0; t < TPG; t++) {
                tb[(2 * t + 0) * 33 + lane] = r0s[t];
                tb[(2 * t + 1) * 33 + lane] = r1s[t];
            }
            __syncwarp();
            {
                const int k    = lane >> 1;
                const int half = lane & 1;
                const float* src = tb + k * 33 + half * 16;
                float a0 = src[0],  a1 = src[1],  a2 = src[2],  a3 = src[3];
                float a4 = src[4],  a5 = src[5],  a6 = src[6],  a7 = src[7];
                float a8 = src[8],  a9 = src[9],  aA = src[10], aB = src[11];
                float aC = src[12], aD = src[13], aE = src[14], aF = src[15];
                float m = fmin3(fmin3(fmin3(a0, a1, a2),  fmin3(a3, a4, a5),  fmin3(a6, a7, a8)),
                                fmin3(fmin3(a9, aA, aB),  fmin3(aC, aD, aE),  aF),
                                3.4e38f);
                m = fminf(m, __shfl_xor_sync(0xFFFFFFFFu, m, 1));
                if (half == 0)
                    atomicMin(&g_rowmin[b * NPTS + row0 + g * 16 + k], flipf(m));
            }
            __syncwarp();
        }

        // Flush colmin partials for this tile
#pragma unroll
        for (int c = 0; c < C; c++)
            atomicMin(&g_colmin[b * NPTS + j0 + c], flipf(cm[c]));
    }
}

// ---------------------------------------------------------------------------
__global__ void finalize_kernel(float* __restrict__ out) {
    int idx = blockIdx.x * blockDim.x + threadIdx.x;

    float local = 0.0f;
    if (idx < NB * NPTS) {
        float vr = unflipf(g_rowmin[idx]);
        float vc = unflipf(g_colmin[idx]);
        local  = sqrtf(EPS + fmaxf(vr, 0.0f));
        local += sqrtf(EPS + fmaxf(vc, 0.0f));
    }

#pragma unroll
    for (int o = 16; o > 0; o >>= 1)
        local += __shfl_down_sync(0xFFFFFFFFu, local, o);

    __shared__ float warp_sums[8];
    int lane = threadIdx.x & 31;
    int wid  = threadIdx.x >> 5;
    if (lane == 0) warp_sums[wid] = local;
    __syncthreads();
    if (wid == 0) {
        float sv = (lane < 8) ? warp_sums[lane] : 0.0f;
#pragma unroll
        for (int o = 4; o > 0; o >>= 1)
            sv += __shfl_down_sync(0xFFFFFFFFu, sv, o);
        if (lane == 0) atomicAdd(out, sv * (1.0f / (float)TOTAL_Q));
    }
}

extern "C" void kernel_launch(void* const* d_in, const int* in_sizes, int n_in,
                              void* d_out, int out_size) {
    const float* x = (const float*)d_in[0];
    const float* y = (const float*)d_in[1];
    float* out = (float*)d_out;

    pack_kernel<<<(NB * NPTS / 4 + 127) / 128, 128>>>(x, y, out);
    chamfer_fused_kernel<<<NBLOCKS, THREADS>>>();
    finalize_kernel<<<(NB * NPTS + 255) / 256, 256>>>(out);
}

// round 15
// speedup vs baseline: 6.4487x; 1.1803x over previous
#include <cuda_runtime.h>
#include <math.h>

#define NB       16
#define NPTS     4096
#define C        4                        // candidates per thread (register-resident)
#define THREADS  128
#define WARPS    (THREADS / 32)
#define CANDS_PER_BLOCK (THREADS * C)     // 512
#define CCHUNKS  (NPTS / CANDS_PER_BLOCK) // 8
#define ROWSPLIT 32
#define ROWS_PER_BLOCK (NPTS / ROWSPLIT)  // 128
#define RPAIRS   (ROWS_PER_BLOCK / 2)     // 64
#define GROUPS   8                        // 16 rows per transpose batch
#define TPG      (RPAIRS / GROUPS)        // 8
#define NTILES   (CCHUNKS * ROWSPLIT * NB)  // 4096
#define NBLOCKS  592                      // 148 SMs x occ 4, single wave
#define EPS      1e-6f
#define TOTAL_Q  (NB * NPTS)

// Scratch (no cudaMalloc allowed)
__device__ float4   g_rowpair[NB * NPTS];      // pair 2k:(x0,x1,y0,y1) 2k+1:(z0,z1,w0,w1)
__device__ float4   g_col[NB * NPTS];          // (-2x, -2y, -2z, ||x||^2)
__device__ unsigned g_rowmin[NB * NPTS];
__device__ unsigned g_colmin[NB * NPTS];

__device__ __forceinline__ unsigned flipf(float f) {
    unsigned b = __float_as_uint(f);
    return b ^ (0x80000000u | (unsigned)((int)b >> 31));
}
__device__ __forceinline__ float unflipf(unsigned u) {
    unsigned b = (u & 0x80000000u) ? (u ^ 0x80000000u) : ~u;
    return __uint_as_float(b);
}
__device__ __forceinline__ unsigned long long pack2(float a, float b) {
    unsigned long long r;
    asm("mov.b64 %0, {%1, %2};" : "=l"(r) : "f"(a), "f"(b));
    return r;
}
__device__ __forceinline__ float fmin3(float a, float b, float c) {
    float r;
    asm("min.f32 %0, %1, %2, %3;" : "=f"(r) : "f"(a), "f"(b), "f"(c));
    return r;
}

// ---------------------------------------------------------------------------
// Pack kernel: thread k handles 4 consecutive points of each tensor
// via 3 coalesced float4 loads per tensor.
// ---------------------------------------------------------------------------
__global__ void pack_kernel(const float* __restrict__ x,
                            const float* __restrict__ y,
                            float* __restrict__ out) {
    int k = blockIdx.x * blockDim.x + threadIdx.x;   // quad index
    if (k == 0) out[0] = 0.0f;
    if (k >= NB * NPTS / 4) return;

    {
        const float4* p = (const float4*)(y) + 3 * k;   // 12 floats = 4 points
        float4 a = p[0], b = p[1], c = p[2];
        float w0 = a.x * a.x + a.y * a.y + a.z * a.z;
        float w1 = a.w * a.w + b.x * b.x + b.y * b.y;
        float w2 = b.z * b.z + b.w * b.w + c.x * c.x;
        float w3 = c.y * c.y + c.z * c.z + c.w * c.w;
        float4* dst = g_rowpair + 4 * k;
        dst[0] = make_float4(a.x, a.w, a.y, b.x);
        dst[1] = make_float4(a.z, b.y, w0, w1);
        dst[2] = make_float4(b.z, c.y, b.w, c.z);
        dst[3] = make_float4(c.x, c.w, w2, w3);
    }
    {
        const float4* p = (const float4*)(x) + 3 * k;
        float4 a = p[0], b = p[1], c = p[2];
        float4* dst = g_col + 4 * k;
        dst[0] = make_float4(-2.f * a.x, -2.f * a.y, -2.f * a.z,
                             a.x * a.x + a.y * a.y + a.z * a.z);
        dst[1] = make_float4(-2.f * a.w, -2.f * b.x, -2.f * b.y,
                             a.w * a.w + b.x * b.x + b.y * b.y);
        dst[2] = make_float4(-2.f * b.z, -2.f * b.w, -2.f * c.x,
                             b.z * b.z + b.w * b.w + c.x * c.x);
        dst[3] = make_float4(-2.f * c.y, -2.f * c.z, -2.f * c.w,
                             c.y * c.y + c.z * c.z + c.w * c.w);
    }
    ((uint4*)(g_rowmin + 4 * k))[0] = make_uint4(~0u, ~0u, ~0u, ~0u);
    ((uint4*)(g_colmin + 4 * k))[0] = make_uint4(~0u, ~0u, ~0u, ~0u);
}

// ---------------------------------------------------------------------------
// Persistent fused pass: 592 blocks, each owns a CONTIGUOUS tile range in
// rs-fastest order. Candidates (512/block, C=4/thread) reload + colmin flush
// only when the (b, cc) key changes. Inner loop = R8 structure at C=4.
// ---------------------------------------------------------------------------
__global__ __launch_bounds__(THREADS, 4)
void chamfer_fused_kernel() {
    __shared__ float4 rowtile[RPAIRS * 2];             // 2 KB
    __shared__ float  tbuf[WARPS][16 * 33];

    const int lane = threadIdx.x & 31;
    const int wid  = threadIdx.x >> 5;
    float* tb = tbuf[wid];
    const ulonglong2* tp = (const ulonglong2*)rowtile;

    const int t0 = (int)(((long long)NTILES * blockIdx.x)       / NBLOCKS);
    const int t1 = (int)(((long long)NTILES * (blockIdx.x + 1)) / NBLOCKS);

    unsigned long long cxd[C], cyd[C], czd[C], cwd[C];
    float cm[C];
    int prev_key = -1, prev_j = 0;

    for (int tile = t0; tile < t1; tile++) {
        const int rs  = tile & (ROWSPLIT - 1);
        const int key = tile >> 5;             // b * CCHUNKS + cc
        const int b   = key >> 3;
        const int row0 = rs * ROWS_PER_BLOCK;

        if (key != prev_key) {
            const int cc = key & (CCHUNKS - 1);
            const int j  = (b << 12) + cc * CANDS_PER_BLOCK + threadIdx.x * C;
            if (prev_key >= 0) {
#pragma unroll
                for (int c = 0; c < C; c++)
                    atomicMin(&g_colmin[prev_j + c], flipf(cm[c]));
            }
            const float4* __restrict__ Cd = g_col + j;
#pragma unroll
            for (int c = 0; c < C; c++) {
                float4 f = Cd[c];
                cxd[c] = pack2(f.x, f.x);
                cyd[c] = pack2(f.y, f.y);
                czd[c] = pack2(f.z, f.z);
                cwd[c] = pack2(f.w, f.w);
                cm[c]  = 3.4e38f;
            }
            prev_key = key;
            prev_j   = j;
        }

        // Stage row slice (sync first: prev tile may still read rowtile)
        __syncthreads();
        {
            const float4* __restrict__ RPbase = g_rowpair + (b << 12) + row0;
            for (int i = threadIdx.x; i < RPAIRS * 2; i += THREADS)
                rowtile[i] = RPbase[i];
        }
        __syncthreads();

        for (int g = 0; g < GROUPS; g++) {
            float r0s[TPG], r1s[TPG];

#pragma unroll
            for (int t = 0; t < TPG; t++) {
                const int rp = g * TPG + t;
                ulonglong2 e0 = tp[2 * rp + 0];   // .x = xpair, .y = ypair
                ulonglong2 e1 = tp[2 * rp + 1];   // .x = zpair, .y = wpair (y2)

                float v0s[C], v1s[C];
#pragma unroll
                for (int c = 0; c < C; c++) {
                    unsigned long long t64;
                    asm("fma.rn.f32x2 %0, %1, %2, %3;" : "=l"(t64) : "l"(e1.x), "l"(czd[c]), "l"(cwd[c]));
                    asm("fma.rn.f32x2 %0, %1, %2, %0;" : "+l"(t64) : "l"(e0.y), "l"(cyd[c]));
                    asm("fma.rn.f32x2 %0, %1, %2, %0;" : "+l"(t64) : "l"(e0.x), "l"(cxd[c]));
                    asm("add.rn.f32x2 %0, %0, %1;"     : "+l"(t64) : "l"(e1.y));
                    float v0, v1;
                    asm("mov.b64 {%0, %1}, %2;" : "=f"(v0), "=f"(v1) : "l"(t64));
                    v0s[c] = v0; v1s[c] = v1;
                    cm[c] = fmin3(cm[c], v0, v1);
                }
                // Row trees over 4 candidates: 2 ops each
                r0s[t] = fminf(fmin3(v0s[0], v0s[1], v0s[2]), v0s[3]);
                r1s[t] = fminf(fmin3(v1s[0], v1s[1], v1s[2]), v1s[3]);
            }

            // ---- Transpose-reduce 16 rows x 32 lanes (per warp) ----
#pragma unroll
            for (int t = 0; t < TPG; t++) {
                tb[(2 * t + 0) * 33 + lane] = r0s[t];
                tb[(2 * t + 1) * 33 + lane] = r1s[t];
            }
            __syncwarp();
            {
                const int k    = lane >> 1;
                const int half = lane & 1;
                const float* src = tb + k * 33 + half * 16;
                float a0 = src[0],  a1 = src[1],  a2 = src[2],  a3 = src[3];
                float a4 = src[4],  a5 = src[5],  a6 = src[6],  a7 = src[7];
                float a8 = src[8],  a9 = src[9],  aA = src[10], aB = src[11];
                float aC = src[12], aD = src[13], aE = src[14], aF = src[15];
                float m = fmin3(fmin3(fmin3(a0, a1, a2),  fmin3(a3, a4, a5),  fmin3(a6, a7, a8)),
                                fmin3(fmin3(a9, aA, aB),  fmin3(aC, aD, aE),  aF),
                                3.4e38f);
                m = fminf(m, __shfl_xor_sync(0xFFFFFFFFu, m, 1));
                if (half == 0)
                    atomicMin(&g_rowmin[(b << 12) + row0 + g * 16 + k], flipf(m));
            }
            __syncwarp();
        }
    }

    // Final colmin flush
    if (prev_key >= 0) {
#pragma unroll
        for (int c = 0; c < C; c++)
            atomicMin(&g_colmin[prev_j + c], flipf(cm[c]));
    }
}

// ---------------------------------------------------------------------------
__global__ void finalize_kernel(float* __restrict__ out) {
    int idx = blockIdx.x * blockDim.x + threadIdx.x;

    float local = 0.0f;
    if (idx < NB * NPTS) {
        float vr = unflipf(g_rowmin[idx]);
        float vc = unflipf(g_colmin[idx]);
        local  = sqrtf(EPS + fmaxf(vr, 0.0f));
        local += sqrtf(EPS + fmaxf(vc, 0.0f));
    }

#pragma unroll
    for (int o = 16; o > 0; o >>= 1)
        local += __shfl_down_sync(0xFFFFFFFFu, local, o);

    __shared__ float warp_sums[8];
    int lane = threadIdx.x & 31;
    int wid  = threadIdx.x >> 5;
    if (lane == 0) warp_sums[wid] = local;
    __syncthreads();
    if (wid == 0) {
        float sv = (lane < 8) ? warp_sums[lane] : 0.0f;
#pragma unroll
        for (int o = 4; o > 0; o >>= 1)
            sv += __shfl_down_sync(0xFFFFFFFFu, sv, o);
        if (lane == 0) atomicAdd(out, sv * (1.0f / (float)TOTAL_Q));
    }
}

extern "C" void kernel_launch(void* const* d_in, const int* in_sizes, int n_in,
                              void* d_out, int out_size) {
    const float* x = (const float*)d_in[0];
    const float* y = (const float*)d_in[1];
    float* out = (float*)d_out;

    pack_kernel<<<(NB * NPTS / 4 + 127) / 128, 128>>>(x, y, out);
    chamfer_fused_kernel<<<NBLOCKS, THREADS>>>();
    finalize_kernel<<<(NB * NPTS + 255) / 256, 256>>>(out);
}

// round 16
// speedup vs baseline: 6.5488x; 1.0155x over previous
#include <cuda_runtime.h>
#include <math.h>

#define NB       16
#define NPTS     4096
#define C        8                        // candidates per thread (register-resident)
#define THREADS  128
#define WARPS    (THREADS / 32)
#define CANDS_PER_BLOCK (THREADS * C)     // 1024
#define CCHUNKS  (NPTS / CANDS_PER_BLOCK) // 4
#define ROWSPLIT 64
#define ROWS_PER_BLOCK (NPTS / ROWSPLIT)  // 64
#define RPAIRS   (ROWS_PER_BLOCK / 2)     // 32
#define GROUPS   4                        // 4 groups of 16 rows
#define TPG      (RPAIRS / GROUPS)        // 8
#define EPS      1e-6f
#define TOTAL_Q  (NB * NPTS)

// Scratch (no cudaMalloc allowed)
__device__ float4   g_rowpair[NB * NPTS];      // pair 2k:(x0,x1,y0,y1) 2k+1:(z0,z1,w0,w1)
__device__ float4   g_col[NB * NPTS];          // (-2x, -2y, -2z, ||x||^2)
__device__ unsigned g_rowmin[NB * NPTS];
__device__ unsigned g_colmin[NB * NPTS];

__device__ __forceinline__ unsigned flipf(float f) {
    unsigned b = __float_as_uint(f);
    return b ^ (0x80000000u | (unsigned)((int)b >> 31));
}
__device__ __forceinline__ float unflipf(unsigned u) {
    unsigned b = (u & 0x80000000u) ? (u ^ 0x80000000u) : ~u;
    return __uint_as_float(b);
}
__device__ __forceinline__ unsigned long long pack2(float a, float b) {
    unsigned long long r;
    asm("mov.b64 %0, {%1, %2};" : "=l"(r) : "f"(a), "f"(b));
    return r;
}
__device__ __forceinline__ float fmin3(float a, float b, float c) {
    float r;
    asm("min.f32 %0, %1, %2, %3;" : "=f"(r) : "f"(a), "f"(b), "f"(c));
    return r;
}

// ---------------------------------------------------------------------------
// Pack kernel: thread k handles 4 consecutive points of each tensor
// via 3 coalesced float4 loads per tensor (R13 version, proven).
// ---------------------------------------------------------------------------
__global__ void pack_kernel(const float* __restrict__ x,
                            const float* __restrict__ y,
                            float* __restrict__ out) {
    int k = blockIdx.x * blockDim.x + threadIdx.x;   // quad index
    if (k == 0) out[0] = 0.0f;
    if (k >= NB * NPTS / 4) return;

    {
        const float4* p = (const float4*)(y) + 3 * k;   // 12 floats = 4 points
        float4 a = p[0], b = p[1], c = p[2];
        float w0 = a.x * a.x + a.y * a.y + a.z * a.z;
        float w1 = a.w * a.w + b.x * b.x + b.y * b.y;
        float w2 = b.z * b.z + b.w * b.w + c.x * c.x;
        float w3 = c.y * c.y + c.z * c.z + c.w * c.w;
        float4* dst = g_rowpair + 4 * k;
        dst[0] = make_float4(a.x, a.w, a.y, b.x);
        dst[1] = make_float4(a.z, b.y, w0, w1);
        dst[2] = make_float4(b.z, c.y, b.w, c.z);
        dst[3] = make_float4(c.x, c.w, w2, w3);
    }
    {
        const float4* p = (const float4*)(x) + 3 * k;
        float4 a = p[0], b = p[1], c = p[2];
        float4* dst = g_col + 4 * k;
        dst[0] = make_float4(-2.f * a.x, -2.f * a.y, -2.f * a.z,
                             a.x * a.x + a.y * a.y + a.z * a.z);
        dst[1] = make_float4(-2.f * a.w, -2.f * b.x, -2.f * b.y,
                             a.w * a.w + b.x * b.x + b.y * b.y);
        dst[2] = make_float4(-2.f * b.z, -2.f * b.w, -2.f * c.x,
                             b.z * b.z + b.w * b.w + c.x * c.x);
        dst[3] = make_float4(-2.f * c.y, -2.f * c.z, -2.f * c.w,
                             c.y * c.y + c.z * c.z + c.w * c.w);
    }
    ((uint4*)(g_rowmin + 4 * k))[0] = make_uint4(~0u, ~0u, ~0u, ~0u);
    ((uint4*)(g_colmin + 4 * k))[0] = make_uint4(~0u, ~0u, ~0u, ~0u);
}

// ---------------------------------------------------------------------------
// Fused pass (R8 inner loop, proven): grid (CCHUNKS, ROWSPLIT, NB) =
// (4, 64, 16) = 4096 blocks — half-height tiles for finer tail granularity.
// Per warp-iter (512 pairs): 32 FFMA2/FADD2 + 8 mov + 16 min3/min; cross-lane
// rowmin once per 16 rows via padded smem transpose.
// ---------------------------------------------------------------------------
__global__ __launch_bounds__(THREADS, 4)
void chamfer_fused_kernel() {
    __shared__ float4 rowtile[RPAIRS * 2];             // 1 KB
    __shared__ float  tbuf[WARPS][16 * 33];

    const int b  = blockIdx.z;
    const int rs = blockIdx.y;
    const int cc = blockIdx.x;

    const int row0 = rs * ROWS_PER_BLOCK;
    const int j0   = cc * CANDS_PER_BLOCK + threadIdx.x * C;

    const float4* __restrict__ RPbase = g_rowpair + (size_t)b * NPTS + row0;
    const float4* __restrict__ Cd     = g_col     + (size_t)b * NPTS + j0;

    unsigned long long cxd[C], cyd[C], czd[C], cwd[C];
    float cm[C];
#pragma unroll
    for (int c = 0; c < C; c++) {
        float4 f = Cd[c];
        cxd[c] = pack2(f.x, f.x);
        cyd[c] = pack2(f.y, f.y);
        czd[c] = pack2(f.z, f.z);
        cwd[c] = pack2(f.w, f.w);
        cm[c]  = 3.4e38f;
    }

    for (int i = threadIdx.x; i < RPAIRS * 2; i += THREADS)
        rowtile[i] = RPbase[i];
    __syncthreads();

    const int lane = threadIdx.x & 31;
    const int wid  = threadIdx.x >> 5;
    float* tb = tbuf[wid];
    const ulonglong2* tp = (const ulonglong2*)rowtile;

    for (int g = 0; g < GROUPS; g++) {
        float r0s[TPG], r1s[TPG];

#pragma unroll
        for (int t = 0; t < TPG; t++) {
            const int rp = g * TPG + t;
            ulonglong2 e0 = tp[2 * rp + 0];   // .x = xpair, .y = ypair
            ulonglong2 e1 = tp[2 * rp + 1];   // .x = zpair, .y = wpair (y2)

            float v0s[C], v1s[C];
#pragma unroll
            for (int c = 0; c < C; c++) {
                unsigned long long t64;
                asm("fma.rn.f32x2 %0, %1, %2, %3;" : "=l"(t64) : "l"(e1.x), "l"(czd[c]), "l"(cwd[c]));
                asm("fma.rn.f32x2 %0, %1, %2, %0;" : "+l"(t64) : "l"(e0.y), "l"(cyd[c]));
                asm("fma.rn.f32x2 %0, %1, %2, %0;" : "+l"(t64) : "l"(e0.x), "l"(cxd[c]));
                asm("add.rn.f32x2 %0, %0, %1;"     : "+l"(t64) : "l"(e1.y));
                float v0, v1;
                asm("mov.b64 {%0, %1}, %2;" : "=f"(v0), "=f"(v1) : "l"(t64));
                v0s[c] = v0; v1s[c] = v1;
                cm[c] = fmin3(cm[c], v0, v1);
            }
            r0s[t] = fmin3(fmin3(v0s[0], v0s[1], v0s[2]),
                           fmin3(v0s[3], v0s[4], v0s[5]),
                           fminf(v0s[6], v0s[7]));
            r1s[t] = fmin3(fmin3(v1s[0], v1s[1], v1s[2]),
                           fmin3(v1s[3], v1s[4], v1s[5]),
                           fminf(v1s[6], v1s[7]));
        }

        // ---- Transpose-reduce 16 rows x 32 lanes (per warp) ----
#pragma unroll
        for (int t = 0; t < TPG; t++) {
            tb[(2 * t + 0) * 33 + lane] = r0s[t];
            tb[(2 * t + 1) * 33 + lane] = r1s[t];
        }
        __syncwarp();
        {
            const int k    = lane >> 1;
            const int half = lane & 1;
            const float* src = tb + k * 33 + half * 16;
            float a0 = src[0],  a1 = src[1],  a2 = src[2],  a3 = src[3];
            float a4 = src[4],  a5 = src[5],  a6 = src[6],  a7 = src[7];
            float a8 = src[8],  a9 = src[9],  aA = src[10], aB = src[11];
            float aC = src[12], aD = src[13], aE = src[14], aF = src[15];
            float m = fmin3(fmin3(fmin3(a0, a1, a2),  fmin3(a3, a4, a5),  fmin3(a6, a7, a8)),
                            fmin3(fmin3(a9, aA, aB),  fmin3(aC, aD, aE),  aF),
                            3.4e38f);
            m = fminf(m, __shfl_xor_sync(0xFFFFFFFFu, m, 1));
            if (half == 0)
                atomicMin(&g_rowmin[b * NPTS + row0 + g * 16 + k], flipf(m));
        }
        __syncwarp();
    }

    // Flush colmin partials
#pragma unroll
    for (int c = 0; c < C; c++)
        atomicMin(&g_colmin[b * NPTS + j0 + c], flipf(cm[c]));
}

// ---------------------------------------------------------------------------
__global__ void finalize_kernel(float* __restrict__ out) {
    int idx = blockIdx.x * blockDim.x + threadIdx.x;

    float local = 0.0f;
    if (idx < NB * NPTS) {
        float vr = unflipf(g_rowmin[idx]);
        float vc = unflipf(g_colmin[idx]);
        local  = sqrtf(EPS + fmaxf(vr, 0.0f));
        local += sqrtf(EPS + fmaxf(vc, 0.0f));
    }

#pragma unroll
    for (int o = 16; o > 0; o >>= 1)
        local += __shfl_down_sync(0xFFFFFFFFu, local, o);

    __shared__ float warp_sums[8];
    int lane = threadIdx.x & 31;
    int wid  = threadIdx.x >> 5;
    if (lane == 0) warp_sums[wid] = local;
    __syncthreads();
    if (wid == 0) {
        float sv = (lane < 8) ? warp_sums[lane] : 0.0f;
#pragma unroll
        for (int o = 4; o > 0; o >>= 1)
            sv += __shfl_down_sync(0xFFFFFFFFu, sv, o);
        if (lane == 0) atomicAdd(out, sv * (1.0f / (float)TOTAL_Q));
    }
}

extern "C" void kernel_launch(void* const* d_in, const int* in_sizes, int n_in,
                              void* d_out, int out_size) {
    const float* x = (const float*)d_in[0];
    const float* y = (const float*)d_in[1];
    float* out = (float*)d_out;

    pack_kernel<<<(NB * NPTS / 4 + 127) / 128, 128>>>(x, y, out);

    dim3 grid(CCHUNKS, ROWSPLIT, NB);   // (4, 64, 16) = 4096 blocks
    chamfer_fused_kernel<<<grid, THREADS>>>();

    finalize_kernel<<<(NB * NPTS + 255) / 256, 256>>>(out);
}